// round 1
// baseline (speedup 1.0000x reference)
#include <cuda_runtime.h>
#include <cuda_bf16.h>

// Problem constants (from reference): N boxes (dynamic), C=256, G=7, dims {38,19,10,5,3,1}
#define ROI_C   256
#define ROI_G   7
#define ROI_GG  49            // 7*7
#define ROI_ELEMS_PER_BOX (ROI_C * ROI_GG)   // 12544
#define BLOCK_THREADS 784     // 16 * 49 ; thread = c0*49 + g
#define C_STRIDE 16           // channels per thread = 256/16

// Per-level cell counts: 256*D*D. Prefix sums (float4 units) -> also offsets into g4buf.
// 38^2=1444, 19^2=361, 10^2=100, 5^2=25, 3^2=9, 1
// 256*1444=369664; +256*361=92416 ->462080; +25600 ->487680; +6400 ->494080; +2304 ->496384; +256 ->496640
#define G4_TOTAL 496640

static __device__ float4 g4buf[G4_TOTAL];   // 7.94 MB scratch, L2-resident

__constant__ int c_bnd[7] = {0, 369664, 462080, 487680, 494080, 496384, 496640};
__constant__ int c_Dc[6]  = {38, 19, 10, 5, 3, 1};

// ---------------------------------------------------------------------------
// Prep: pack the 4 bilinear corners of every cell (x,y) of every fmap level
// into one float4:  (v[x,y], v[x,y+1], v[x+1,y], v[x+1,y+1]), edge-clamped.
// ---------------------------------------------------------------------------
__global__ void prep_kernel(const float* __restrict__ f0, const float* __restrict__ f1,
                            const float* __restrict__ f2, const float* __restrict__ f3,
                            const float* __restrict__ f4, const float* __restrict__ f5) {
    int idx = blockIdx.x * blockDim.x + threadIdx.x;
    if (idx >= G4_TOTAL) return;

    int l = 0;
    #pragma unroll
    for (int j = 1; j < 6; ++j) l += (idx >= c_bnd[j]) ? 1 : 0;

    const float* f = f0;
    if (l == 1) f = f1;
    else if (l == 2) f = f2;
    else if (l == 3) f = f3;
    else if (l == 4) f = f4;
    else if (l == 5) f = f5;

    int local = idx - c_bnd[l];
    int D  = c_Dc[l];
    int DD = D * D;
    int c   = local / DD;
    int rem = local - c * DD;
    int x   = rem / D;
    int y   = rem - x * D;

    const float* fc = f + c * DD;
    int xp = min(x + 1, D - 1);
    int yp = min(y + 1, D - 1);

    g4buf[idx] = make_float4(fc[x * D + y],  fc[x * D + yp],
                             fc[xp * D + y], fc[xp * D + yp]);
}

// ---------------------------------------------------------------------------
// Main: one block per box. tid = c0*49 + g, g fixed per thread -> weights and
// cell offset live in registers across the 16-channel loop.
// Inner loop: 1x LDG.128 + 4 FMA + 1x coalesced STG.32 per output element.
// ---------------------------------------------------------------------------
__global__ __launch_bounds__(BLOCK_THREADS)
void roi_kernel(const float* __restrict__ boxes, float* __restrict__ out) {
    const int n   = blockIdx.x;
    const int tid = threadIdx.x;

    // Box (broadcast loads, L1-hit for all threads of the block)
    const float bx1 = __ldg(boxes + 4 * n + 0);
    const float by1 = __ldg(boxes + 4 * n + 1);
    const float bx2 = __ldg(boxes + 4 * n + 2);
    const float by2 = __ldg(boxes + 4 * n + 3);

    // Level selection: clip(floor(5 + log2(sqrt(w*h))), 0, 5)   (float32, as reference)
    const float avg = sqrtf((bx2 - bx1) * (by2 - by1));
    int lvl = (int)floorf(5.0f + log2f(avg));
    lvl = max(0, min(5, lvl));

    const int D    = c_Dc[lvl];
    const int DD   = D * D;
    const int base = c_bnd[lvl];

    // Thread decomposition: tid = c0*49 + g ; g = gi*7 + gj
    const int c0 = tid / ROI_GG;
    const int g  = tid - c0 * ROI_GG;
    const int gi = g / ROI_G;
    const int gj = g - gi * ROI_G;

    // Sample coords, exactly matching reference arithmetic:
    //   xr = clip(x1 + t*(x2-x1)/6, 0, 1); ux = xr*(D-1)
    //   x0 = floor(ux); px0 = 1-(ux-x0); px1 = 1-px0  (ddx==1 always)
    const float Dm1 = (float)(D - 1);
    const float fx = fminf(fmaxf(bx1 + ((float)gi * (bx2 - bx1)) / 6.0f, 0.0f), 1.0f);
    const float fy = fminf(fmaxf(by1 + ((float)gj * (by2 - by1)) / 6.0f, 0.0f), 1.0f);
    const float ux = fx * Dm1;
    const float uy = fy * Dm1;
    const float x0f = floorf(ux);
    const float y0f = floorf(uy);
    const float px0 = 1.0f - (ux - x0f);
    const float px1 = 1.0f - px0;
    const float py0 = 1.0f - (uy - y0f);
    const float py1 = 1.0f - py0;
    const int ix0 = (int)x0f;
    const int iy0 = (int)y0f;

    // Weights in G4 component order: (tl, bl, tr, br) = (x,y) (x,y+1) (x+1,y) (x+1,y+1)
    const float w0 = px0 * py0;
    const float w1 = px0 * py1;
    const float w2 = px1 * py0;
    const float w3 = px1 * py1;

    const float4* gp = g4buf + base + ix0 * D + iy0 + c0 * DD;
    float*        op = out + (size_t)n * ROI_ELEMS_PER_BOX + tid;
    const int     gstride = C_STRIDE * DD;   // advance 16 channels per iter

    #pragma unroll 4
    for (int k = 0; k < ROI_C / C_STRIDE; ++k) {
        const float4 p = __ldg(gp + k * gstride);
        op[k * BLOCK_THREADS] = w0 * p.x + w1 * p.y + w2 * p.z + w3 * p.w;
    }
}

// ---------------------------------------------------------------------------
// Launcher. Inputs (metadata order): boxes, fmap0..fmap5. Output: float32.
// Graph-capturable: two kernel launches on the capture stream, no allocs.
// ---------------------------------------------------------------------------
extern "C" void kernel_launch(void* const* d_in, const int* in_sizes, int n_in,
                              void* d_out, int out_size) {
    const float* boxes = (const float*)d_in[0];
    const float* f0 = (const float*)d_in[1];
    const float* f1 = (const float*)d_in[2];
    const float* f2 = (const float*)d_in[3];
    const float* f3 = (const float*)d_in[4];
    const float* f4 = (const float*)d_in[5];
    const float* f5 = (const float*)d_in[6];

    const int N = in_sizes[0] / 4;   // boxes are [N,4]

    prep_kernel<<<(G4_TOTAL + 255) / 256, 256>>>(f0, f1, f2, f3, f4, f5);
    roi_kernel<<<N, BLOCK_THREADS>>>(boxes, (float*)d_out);
}